// round 3
// baseline (speedup 1.0000x reference)
#include <cuda_runtime.h>

#define BB 256
#define SS 512
#define TT 128

// Scratch (no allocations allowed in kernel_launch)
__device__ float g_E[TT * TT];     // exp(transitions)
__device__ float g_gold[BB];       // per-batch gold score
__device__ float g_logZ[BB];       // per-batch log partition
__device__ int   g_tagStride;      // 1 = int32 tags, 2 = int64 tags (stride in i32 words)

// ---------------------------------------------------------------------------
// Kernel 0: detect tag dtype. If tags are int64 (values < 128, little-endian),
// every odd 32-bit word of the buffer is 0. For int32 tags the odd words are
// real tags (all-zero probability ~ (1/128)^256 ~ 0).
// ---------------------------------------------------------------------------
__global__ void detect_tags_kernel(const unsigned int* __restrict__ tags32) {
    unsigned int acc = 0;
    for (int i = threadIdx.x; i < 256; i += 32)
        acc |= tags32[2 * i + 1];
    #pragma unroll
    for (int o = 16; o > 0; o >>= 1)
        acc |= __shfl_xor_sync(0xffffffffu, acc, o);
    if (threadIdx.x == 0) g_tagStride = (acc == 0u) ? 2 : 1;
}

// ---------------------------------------------------------------------------
// Kernel 1: E = exp(transitions)
// ---------------------------------------------------------------------------
__global__ void expT_kernel(const float* __restrict__ trans) {
    int i = blockIdx.x * blockDim.x + threadIdx.x;
    if (i < TT * TT) g_E[i] = __expf(trans[i]);
}

// ---------------------------------------------------------------------------
// Kernel 2: gold score per batch
// emit_sc = sum_s emissions[b,s,tags[b,s]]
// trans_sc = sum_s transitions[tags[b,s], tags[b,s+1]]
// Tags read as int32 words with runtime stride (1=int32 buffer, 2=int64).
// ---------------------------------------------------------------------------
__global__ void gold_kernel(const float* __restrict__ emis,
                            const int* __restrict__ tags,
                            const float* __restrict__ trans) {
    int b = blockIdx.x;
    int tid = threadIdx.x;
    int lane = tid & 31;
    int wid = tid >> 5;

    const int stride = g_tagStride;
    const int* tg = tags + b * SS * stride;
    const float* eb = emis + (size_t)b * SS * TT;

    float sum = 0.f;
    for (int s = tid; s < SS; s += blockDim.x) {
        int cur = tg[s * stride];
        sum += eb[s * TT + cur];
        if (s < SS - 1) {
            int nxt = tg[(s + 1) * stride];
            sum += trans[cur * TT + nxt];
        }
    }
    // block reduce (128 threads = 4 warps)
    #pragma unroll
    for (int o = 16; o > 0; o >>= 1)
        sum += __shfl_xor_sync(0xffffffffu, sum, o);
    __shared__ float red[4];
    if (lane == 0) red[wid] = sum;
    __syncthreads();
    if (tid == 0) g_gold[b] = red[0] + red[1] + red[2] + red[3];
}

// ---------------------------------------------------------------------------
// Kernel 3: forward algorithm. One CTA per batch, thread t owns alpha[t].
// E column kept in 128 registers per thread.
// alpha'[t] = log( sum_i exp(alpha[i]-m) * E[i][t] ) + m + e[t]
// sp is double-buffered so only 2 barriers per step are needed.
// ---------------------------------------------------------------------------
__global__ void __launch_bounds__(TT, 2) forward_kernel(const float* __restrict__ emis) {
    int b = blockIdx.x;
    int t = threadIdx.x;
    int lane = t & 31;
    int wid = t >> 5;

    __shared__ __align__(16) float sp[2][TT];
    __shared__ float smax[4];
    __shared__ float ssum[4];

    // Load E column t into registers: Ec[i] = exp(T[i][t])
    float Ec[TT];
    #pragma unroll
    for (int i = 0; i < TT; i++) Ec[i] = g_E[i * TT + t];

    const float* eb = emis + (size_t)b * SS * TT;

    float alpha = eb[t];            // alpha0 = emissions[b,0,:]
    float e_cur = eb[TT + t];       // emissions for step s=1

    for (int s = 1; s < SS; s++) {
        // prefetch next step's emission a full iteration early
        float e_next = (s + 1 < SS) ? eb[(s + 1) * TT + t] : 0.f;

        // m = max over all 128 alphas
        float m = alpha;
        #pragma unroll
        for (int o = 16; o > 0; o >>= 1)
            m = fmaxf(m, __shfl_xor_sync(0xffffffffu, m, o));
        if (lane == 0) smax[wid] = m;
        __syncthreads();                               // barrier 1
        m = fmaxf(fmaxf(smax[0], smax[1]), fmaxf(smax[2], smax[3]));

        float* buf = sp[s & 1];
        buf[t] = __expf(alpha - m);
        __syncthreads();                               // barrier 2

        // acc = sum_i p[i] * Ec[i], 4 accumulators to break FMA dependency
        float a0 = 0.f, a1 = 0.f, a2 = 0.f, a3 = 0.f;
        const float4* sp4 = (const float4*)buf;
        #pragma unroll
        for (int i = 0; i < TT / 4; i++) {
            float4 pv = sp4[i];
            a0 = fmaf(pv.x, Ec[4 * i + 0], a0);
            a1 = fmaf(pv.y, Ec[4 * i + 1], a1);
            a2 = fmaf(pv.z, Ec[4 * i + 2], a2);
            a3 = fmaf(pv.w, Ec[4 * i + 3], a3);
        }
        float acc = (a0 + a1) + (a2 + a3);

        alpha = __logf(acc) + m + e_cur;
        e_cur = e_next;
        // No WAR barrier needed: buffer s&1 is next written at step s+2,
        // and step s+1 contains two barriers in between.
    }

    // logZ = logsumexp over final alpha
    float m = alpha;
    #pragma unroll
    for (int o = 16; o > 0; o >>= 1)
        m = fmaxf(m, __shfl_xor_sync(0xffffffffu, m, o));
    if (lane == 0) smax[wid] = m;
    __syncthreads();
    m = fmaxf(fmaxf(smax[0], smax[1]), fmaxf(smax[2], smax[3]));

    float v = __expf(alpha - m);
    #pragma unroll
    for (int o = 16; o > 0; o >>= 1)
        v += __shfl_xor_sync(0xffffffffu, v, o);
    if (lane == 0) ssum[wid] = v;
    __syncthreads();
    if (t == 0)
        g_logZ[b] = __logf(ssum[0] + ssum[1] + ssum[2] + ssum[3]) + m;
}

// ---------------------------------------------------------------------------
// Kernel 4: final scalar: mean_b(-gold[b] + logZ[b])
// ---------------------------------------------------------------------------
__global__ void finalize_kernel(float* __restrict__ out) {
    int t = threadIdx.x;   // 256 threads
    int lane = t & 31;
    int wid = t >> 5;

    float v = -g_gold[t] + g_logZ[t];
    #pragma unroll
    for (int o = 16; o > 0; o >>= 1)
        v += __shfl_xor_sync(0xffffffffu, v, o);
    __shared__ float red[8];
    if (lane == 0) red[wid] = v;
    __syncthreads();
    if (t == 0) {
        float total = 0.f;
        #pragma unroll
        for (int w = 0; w < 8; w++) total += red[w];
        out[0] = total / (float)BB;
    }
}

// ---------------------------------------------------------------------------
extern "C" void kernel_launch(void* const* d_in, const int* in_sizes, int n_in,
                              void* d_out, int out_size) {
    const float* emis  = (const float*)d_in[0];   // (256, 512, 128) f32
    const int*   tags  = (const int*)d_in[1];     // (256, 512) i32 or i64 (detected)
    const float* trans = (const float*)d_in[2];   // (128, 128) f32
    float* out = (float*)d_out;

    detect_tags_kernel<<<1, 32>>>((const unsigned int*)tags);
    expT_kernel<<<(TT * TT + 127) / 128, 128>>>(trans);
    gold_kernel<<<BB, 128>>>(emis, tags, trans);
    forward_kernel<<<BB, TT>>>(emis);
    finalize_kernel<<<1, BB>>>(out);
}

// round 4
// speedup vs baseline: 1.2208x; 1.2208x over previous
#include <cuda_runtime.h>

#define BB 256
#define SS 512
#define TT 128

// Scratch (no allocations allowed in kernel_launch)
__device__ __align__(16) float g_ET[TT * TT];  // transposed exp(transitions): g_ET[t*TT+i] = exp(T[i][t])
__device__ float g_gold[BB];
__device__ float g_logZ[BB];
__device__ int   g_tagStride;      // 1 = int32 tags, 2 = int64 tags

// ---------------------------------------------------------------------------
// Kernel 0: detect tag dtype (odd 32-bit words all zero => int64 buffer)
// ---------------------------------------------------------------------------
__global__ void detect_tags_kernel(const unsigned int* __restrict__ tags32) {
    unsigned int acc = 0;
    for (int i = threadIdx.x; i < 256; i += 32)
        acc |= tags32[2 * i + 1];
    #pragma unroll
    for (int o = 16; o > 0; o >>= 1)
        acc |= __shfl_xor_sync(0xffffffffu, acc, o);
    if (threadIdx.x == 0) g_tagStride = (acc == 0u) ? 2 : 1;
}

// ---------------------------------------------------------------------------
// Kernel 1: g_ET[t][i] = exp(trans[i][t])   (transposed for contiguous columns)
// ---------------------------------------------------------------------------
__global__ void expT_kernel(const float* __restrict__ trans) {
    int i = blockIdx.x * blockDim.x + threadIdx.x;
    if (i < TT * TT) {
        int r = i >> 7;        // row in trans
        int c = i & (TT - 1);  // col in trans
        g_ET[c * TT + r] = __expf(trans[i]);
    }
}

// ---------------------------------------------------------------------------
// Kernel 2: gold score per batch
// ---------------------------------------------------------------------------
__global__ void gold_kernel(const float* __restrict__ emis,
                            const int* __restrict__ tags,
                            const float* __restrict__ trans) {
    int b = blockIdx.x;
    int tid = threadIdx.x;
    int lane = tid & 31;
    int wid = tid >> 5;

    const int stride = g_tagStride;
    const int* tg = tags + b * SS * stride;
    const float* eb = emis + (size_t)b * SS * TT;

    float sum = 0.f;
    for (int s = tid; s < SS; s += blockDim.x) {
        int cur = tg[s * stride];
        sum += eb[s * TT + cur];
        if (s < SS - 1) {
            int nxt = tg[(s + 1) * stride];
            sum += trans[cur * TT + nxt];
        }
    }
    #pragma unroll
    for (int o = 16; o > 0; o >>= 1)
        sum += __shfl_xor_sync(0xffffffffu, sum, o);
    __shared__ float red[4];
    if (lane == 0) red[wid] = sum;
    __syncthreads();
    if (tid == 0) g_gold[b] = red[0] + red[1] + red[2] + red[3];
}

// ---------------------------------------------------------------------------
// Kernel 3: forward algorithm. 1 CTA / batch, thread t owns alpha[t].
// Shift m = thread 0's alpha from 1-2 steps back (block-consistent; exact
// rescaling, only needs to keep exp() in fp32 range). One barrier per step.
// Dot product uses packed fma.rn.f32x2: 64 FFMA2 instead of 128 FFMA.
// ---------------------------------------------------------------------------
__global__ void __launch_bounds__(TT, 2) forward_kernel(const float* __restrict__ emis) {
    int b = blockIdx.x;
    int t = threadIdx.x;
    int lane = t & 31;
    int wid = t >> 5;

    __shared__ __align__(16) float sp[2][TT];
    __shared__ float moff[2];
    __shared__ float smax[4];
    __shared__ float ssum[4];

    // E column t, packed as 64 f32x2 register pairs
    unsigned long long Ep[TT / 2];
    {
        const ulonglong2* ec = (const ulonglong2*)(g_ET + t * TT);
        #pragma unroll
        for (int k = 0; k < TT / 4; k++) {
            ulonglong2 v = ec[k];
            Ep[2 * k]     = v.x;
            Ep[2 * k + 1] = v.y;
        }
    }

    const float* eb = emis + (size_t)b * SS * TT;

    float alpha = eb[t];                 // alpha0
    if (t == 0) moff[0] = alpha;
    float e_cur = eb[TT + t];
    __syncthreads();
    float m = moff[0];                   // initial shift = alpha0[0]

    for (int s = 1; s < SS; s++) {
        float e_next = (s + 1 < SS) ? eb[(s + 1) * TT + t] : 0.f;

        float* buf = sp[s & 1];
        buf[t] = __expf(alpha - m);
        if (t == 0) moff[s & 1] = alpha; // shift for step s+1 (lag 1)
        __syncthreads();                 // the ONLY barrier per step
        float m_next = moff[s & 1];

        // acc = sum_i p[i] * E[i][t], packed pairs, 4 accumulators
        unsigned long long acc0 = 0ull, acc1 = 0ull, acc2 = 0ull, acc3 = 0ull;
        const ulonglong2* sp2 = (const ulonglong2*)buf;
        #pragma unroll
        for (int k = 0; k < TT / 4; k++) {
            ulonglong2 pv = sp2[k];
            if (k & 1) {
                asm("fma.rn.f32x2 %0, %1, %2, %0;" : "+l"(acc2) : "l"(pv.x), "l"(Ep[2 * k]));
                asm("fma.rn.f32x2 %0, %1, %2, %0;" : "+l"(acc3) : "l"(pv.y), "l"(Ep[2 * k + 1]));
            } else {
                asm("fma.rn.f32x2 %0, %1, %2, %0;" : "+l"(acc0) : "l"(pv.x), "l"(Ep[2 * k]));
                asm("fma.rn.f32x2 %0, %1, %2, %0;" : "+l"(acc1) : "l"(pv.y), "l"(Ep[2 * k + 1]));
            }
        }
        float l0, h0, l1, h1, l2, h2, l3, h3;
        asm("mov.b64 {%0,%1}, %2;" : "=f"(l0), "=f"(h0) : "l"(acc0));
        asm("mov.b64 {%0,%1}, %2;" : "=f"(l1), "=f"(h1) : "l"(acc1));
        asm("mov.b64 {%0,%1}, %2;" : "=f"(l2), "=f"(h2) : "l"(acc2));
        asm("mov.b64 {%0,%1}, %2;" : "=f"(l3), "=f"(h3) : "l"(acc3));
        float acc = ((l0 + h0) + (l1 + h1)) + ((l2 + h2) + (l3 + h3));

        alpha = __logf(acc) + m + e_cur;
        e_cur = e_next;
        m = m_next;
    }

    // logZ = logsumexp over final alpha (exact max here)
    float mx = alpha;
    #pragma unroll
    for (int o = 16; o > 0; o >>= 1)
        mx = fmaxf(mx, __shfl_xor_sync(0xffffffffu, mx, o));
    if (lane == 0) smax[wid] = mx;
    __syncthreads();
    mx = fmaxf(fmaxf(smax[0], smax[1]), fmaxf(smax[2], smax[3]));

    float v = __expf(alpha - mx);
    #pragma unroll
    for (int o = 16; o > 0; o >>= 1)
        v += __shfl_xor_sync(0xffffffffu, v, o);
    if (lane == 0) ssum[wid] = v;
    __syncthreads();
    if (t == 0)
        g_logZ[b] = __logf(ssum[0] + ssum[1] + ssum[2] + ssum[3]) + mx;
}

// ---------------------------------------------------------------------------
// Kernel 4: final scalar: mean_b(-gold[b] + logZ[b])
// ---------------------------------------------------------------------------
__global__ void finalize_kernel(float* __restrict__ out) {
    int t = threadIdx.x;   // 256 threads
    int lane = t & 31;
    int wid = t >> 5;

    float v = -g_gold[t] + g_logZ[t];
    #pragma unroll
    for (int o = 16; o > 0; o >>= 1)
        v += __shfl_xor_sync(0xffffffffu, v, o);
    __shared__ float red[8];
    if (lane == 0) red[wid] = v;
    __syncthreads();
    if (t == 0) {
        float total = 0.f;
        #pragma unroll
        for (int w = 0; w < 8; w++) total += red[w];
        out[0] = total / (float)BB;
    }
}

// ---------------------------------------------------------------------------
extern "C" void kernel_launch(void* const* d_in, const int* in_sizes, int n_in,
                              void* d_out, int out_size) {
    const float* emis  = (const float*)d_in[0];   // (256, 512, 128) f32
    const int*   tags  = (const int*)d_in[1];     // (256, 512) i32/i64 (detected)
    const float* trans = (const float*)d_in[2];   // (128, 128) f32
    float* out = (float*)d_out;

    detect_tags_kernel<<<1, 32>>>((const unsigned int*)tags);
    expT_kernel<<<(TT * TT + 127) / 128, 128>>>(trans);
    gold_kernel<<<BB, 128>>>(emis, tags, trans);
    forward_kernel<<<BB, TT>>>(emis);
    finalize_kernel<<<1, BB>>>(out);
}